// round 6
// baseline (speedup 1.0000x reference)
#include <cuda_runtime.h>

// Problem constants (shapes fixed by the dataset)
#define BATCH 64
#define FT    51200            // 80 * 640 elements per (channel,batch) slab
#define BFT   3276800          // 64*80*640 per-channel flattened length
#define NAUX  32
#define WPB   1600             // FT/32 bitset words per batch
#define NPAIR 2048             // NAUX * BATCH
#define NFIFTH 5               // aux slab split
#define F4_PER_FIFTH 2560      // 12800/5
#define AUX_F4_PER_WARP 320    // 2560/8 warps
#define AUX_NBLK (NPAIR * NFIFTH)   // 10240
// Strain: flat over the whole buffer (word index == global_elem/32, batch-free)
#define STR_NBLK 640
#define STR_F4_PER_WARP 160    // 819200 f4 / (640*8 warps)
#define FULLM 0xffffffffu

// Largest float strictly below 20.0f: (x > TH_LT) <=> (x >= 20.0f)
#define TH_LT __int_as_float(0x419FFFFF)

// Scratch (__device__ globals — no allocations). g_done self-resets to 0 each
// launch (last block), so every graph replay sees identical state.
__device__ unsigned g_sbits[BATCH * WPB];
__device__ int g_pi[AUX_NBLK];   // partial intersections
__device__ int g_pc[AUX_NBLK];   // partial aux peak counts
__device__ int g_pa[AUX_NBLK];   // partial 8*c1 accumulators
__device__ unsigned g_done = 0;

__device__ __forceinline__ float finf() { return __int_as_float(0x7f800000); }

__device__ __forceinline__ unsigned nib4(float4 v, float l, float r) {
    unsigned b0 = (v.x > fmaxf(fmaxf(l,   v.y), TH_LT)) ? 1u : 0u;
    unsigned b1 = (v.y > fmaxf(fmaxf(v.x, v.z), TH_LT)) ? 2u : 0u;
    unsigned b2 = (v.z > fmaxf(fmaxf(v.y, v.w), TH_LT)) ? 4u : 0u;
    unsigned b3 = (v.w > fmaxf(fmaxf(v.z, r),   TH_LT)) ? 8u : 0u;
    return (b0 | b1) | (b2 | b3);
}

// ---------------------------------------------------------------------------
// Strain kernel: build the peak bitset, batch-agnostic flat indexing.
// 640 blocks x 256 thr, 8 blocks/SM -> single wave, 64 warps/SM.
// Each warp owns 160 contiguous float4s (5 iterations), register carry for
// cross-iteration neighbors, 2 scalar boundary loads per warp.
// ---------------------------------------------------------------------------
__global__ __launch_bounds__(256, 8) void strain_kernel(const float* __restrict__ s) {
    const int tid = threadIdx.x, lane = tid & 31, w = tid >> 5;
    const int warp_id = blockIdx.x * 8 + w;

    const int q0 = warp_id * STR_F4_PER_WARP;        // first global float4
    const int gelem = q0 * 4;
    const float4* p4 = reinterpret_cast<const float4*>(s) + q0;
    unsigned* wp = g_sbits + (q0 >> 3) + (lane >> 3);
    const int sh = (lane & 7) << 2;

    float carry = (gelem == 0) ? finf() : __ldg(s + gelem - 1);
    const float rlast = (gelem + 4 * STR_F4_PER_WARP == BFT)
                            ? finf()
                            : __ldg(s + gelem + 4 * STR_F4_PER_WARP);
    float4 v = p4[lane];
#pragma unroll
    for (int it = 0; it < 5; ++it) {
        float4 vn = v;
        if (it < 4) vn = p4[(it + 1) * 32 + lane];
        float l = __shfl_up_sync(FULLM, v.w, 1);
        if (lane == 0) l = carry;
        float r = __shfl_down_sync(FULLM, v.x, 1);
        float r31 = (it < 4) ? __shfl_sync(FULLM, vn.x, 0) : rlast;
        if (lane == 31) r = r31;
        carry = __shfl_sync(FULLM, v.w, 31);

        unsigned word = nib4(v, l, r) << sh;
        word |= __shfl_xor_sync(FULLM, word, 1);
        word |= __shfl_xor_sync(FULLM, word, 2);
        word |= __shfl_xor_sync(FULLM, word, 4);
        if ((lane & 7) == 0) wp[it * 4] = word;
        v = vn;
    }
}

// ---------------------------------------------------------------------------
// Aux kernel: 10240 blocks (2048 pairs x 5 fifths), 256 threads. Streams
// 10240 elements/block evict-first, ANDs peak nibbles against the L2-resident
// strain bitset, writes 3 int partials. The LAST block (atomic ticket) sums
// all partials and writes the 4096 outputs, then resets the ticket.
// ---------------------------------------------------------------------------
__global__ __launch_bounds__(256, 8) void aux_kernel(const float* __restrict__ aux,
                                                     float* __restrict__ out,
                                                     int half) {
    const int blk = blockIdx.x;
    const int pair = blk / NFIFTH, fifth = blk - pair * NFIFTH;
    const int b = pair & 63, n = pair >> 6;
    const int tid = threadIdx.x, lane = tid & 31, w = tid >> 5;

    const float* ch = aux + (size_t)n * BFT;
    const int slab4 = fifth * F4_PER_FIFTH + w * AUX_F4_PER_WARP;
    const int gelem = b * FT + slab4 * 4;
    const float4* p4 = reinterpret_cast<const float4*>(ch + gelem);
    const unsigned* __restrict__ swp = g_sbits + b * WPB + (slab4 >> 3) + (lane >> 3);
    const int sh = (lane & 7) << 2;

    float carry = (gelem == 0) ? finf() : __ldg(ch + gelem - 1);
    const float rlast = (gelem + 4 * AUX_F4_PER_WARP == BFT)
                            ? finf()
                            : __ldg(ch + gelem + 4 * AUX_F4_PER_WARP);
    int inter = 0, c2 = 0, c1a = 0;
    float4 v = __ldcs(&p4[lane]);
#pragma unroll
    for (int it = 0; it < 10; ++it) {
        float4 vn = v;
        if (it < 9) vn = __ldcs(&p4[(it + 1) * 32 + lane]);
        float l = __shfl_up_sync(FULLM, v.w, 1);
        if (lane == 0) l = carry;
        float r = __shfl_down_sync(FULLM, v.x, 1);
        float r31 = (it < 9) ? __shfl_sync(FULLM, vn.x, 0) : rlast;
        if (lane == 31) r = r31;
        carry = __shfl_sync(FULLM, v.w, 31);

        unsigned nib = nib4(v, l, r);
        unsigned sw = __ldg(swp + it * 4);            // 8 lanes broadcast same word
        inter += __popc((sw >> sh) & nib);
        c2 += __popc(nib);
        c1a += __popc(sw);                            // sums to 8*c1 over the slab
        v = vn;
    }

    // Block reduce 3 ints (8 warps).
    __shared__ int sm0[8], sm1[8], sm2[8];
#pragma unroll
    for (int o = 16; o > 0; o >>= 1) {
        inter += __shfl_down_sync(FULLM, inter, o);
        c2    += __shfl_down_sync(FULLM, c2, o);
        c1a   += __shfl_down_sync(FULLM, c1a, o);
    }
    if (lane == 0) { sm0[w] = inter; sm1[w] = c2; sm2[w] = c1a; }
    __syncthreads();
    __shared__ bool isLast;
    if (tid == 0) {
        int a = 0, bb = 0, c = 0;
#pragma unroll
        for (int k = 0; k < 8; ++k) { a += sm0[k]; bb += sm1[k]; c += sm2[k]; }
        g_pi[blk] = a; g_pc[blk] = bb; g_pa[blk] = c;
        __threadfence();
        unsigned t = atomicAdd(&g_done, 1u);
        isLast = (t == AUX_NBLK - 1);
    }
    __syncthreads();

    if (isLast) {
        if (tid == 0) g_done = 0;                     // reset for next replay
        // Finalize all 2048 pairs: 8 per thread.
        for (int idx = tid; idx < NPAIR; idx += 256) {
            int ti = 0, tc = 0, ta = 0;
#pragma unroll
            for (int k = 0; k < NFIFTH; ++k) {
                ti += g_pi[idx * NFIFTH + k];
                tc += g_pc[idx * NFIFTH + k];
                ta += g_pa[idx * NFIFTH + k];
            }
            const int c1 = ta >> 3;
            const int uni = c1 + tc - ti;
            float jac, ratio;
            if (uni == 0) {
                jac = 1.0f; ratio = 1.0f;             // empty-vs-empty
            } else {
                jac = (float)ti / (float)uni;
                ratio = (c1 == 0) ? 0.0f : (float)ti / (float)c1;  // 0/0 -> 0
            }
            out[idx] = jac;
            out[half + idx] = ratio;
        }
    }
}

extern "C" void kernel_launch(void* const* d_in, const int* in_sizes, int n_in,
                              void* d_out, int out_size) {
    const float* strain = (const float*)d_in[0];
    const float* aux    = (const float*)d_in[1];
    if (n_in >= 2 && in_sizes[0] != BFT) {            // defensive order check
        strain = (const float*)d_in[1];
        aux    = (const float*)d_in[0];
    }
    float* out = (float*)d_out;

    strain_kernel<<<STR_NBLK, 256>>>(strain);
    aux_kernel<<<AUX_NBLK, 256>>>(aux, out, out_size >> 1);
}

// round 7
// speedup vs baseline: 1.0441x; 1.0441x over previous
#include <cuda_runtime.h>

// Problem constants (shapes fixed by the dataset)
#define BATCH 64
#define FT    51200            // 80 * 640 elements per (channel,batch) slab
#define BFT   3276800          // 64*80*640 per-channel flattened length
#define NAUX  32
#define WPB   1600             // FT/32 bitset words per batch
#define NPAIR 2048             // NAUX * BATCH
#define NFIFTH 5               // aux slab split
#define F4_PER_FIFTH 2560      // 12800/5
#define AUX_F4_PER_WARP 320    // 2560/8 warps
#define AUX_NBLK (NPAIR * NFIFTH)   // 10240
// Strain: flat over the whole buffer (word index == global_elem/32, batch-free)
#define STR_NBLK 640
#define STR_F4_PER_WARP 160    // 819200 f4 / (640*8 warps)
#define FULLM 0xffffffffu

// Largest float strictly below 20.0f: (x > TH_LT) <=> (x >= 20.0f)
#define TH_LT __int_as_float(0x419FFFFF)

// Scratch (__device__ globals — no allocations). g_done self-resets to 0 each
// launch (last block), so every graph replay sees identical state.
__device__ unsigned g_sbits[BATCH * WPB];
__device__ int g_pi[AUX_NBLK];   // partial intersections
__device__ int g_pc[AUX_NBLK];   // partial aux peak counts
__device__ int g_pa[AUX_NBLK];   // partial 8*c1 accumulators
__device__ unsigned g_done = 0;

__device__ __forceinline__ float finf() { return __int_as_float(0x7f800000); }

__device__ __forceinline__ unsigned nib4(float4 v, float l, float r) {
    unsigned b0 = (v.x > fmaxf(fmaxf(l,   v.y), TH_LT)) ? 1u : 0u;
    unsigned b1 = (v.y > fmaxf(fmaxf(v.x, v.z), TH_LT)) ? 2u : 0u;
    unsigned b2 = (v.z > fmaxf(fmaxf(v.y, v.w), TH_LT)) ? 4u : 0u;
    unsigned b3 = (v.w > fmaxf(fmaxf(v.z, r),   TH_LT)) ? 8u : 0u;
    return (b0 | b1) | (b2 | b3);
}

// ---------------------------------------------------------------------------
// Strain kernel: build the peak bitset, batch-agnostic flat indexing.
// 640 blocks x 256 thr, up to 8 blocks/SM (latency-bound: wants warps).
// Each warp owns 160 contiguous float4s (5 iterations), register carry for
// cross-iteration neighbors, 2 scalar boundary loads per warp.
// ---------------------------------------------------------------------------
__global__ __launch_bounds__(256, 8) void strain_kernel(const float* __restrict__ s) {
    const int tid = threadIdx.x, lane = tid & 31, w = tid >> 5;
    const int warp_id = blockIdx.x * 8 + w;

    const int q0 = warp_id * STR_F4_PER_WARP;        // first global float4
    const int gelem = q0 * 4;
    const float4* p4 = reinterpret_cast<const float4*>(s) + q0;
    unsigned* wp = g_sbits + (q0 >> 3) + (lane >> 3);
    const int sh = (lane & 7) << 2;

    float carry = (gelem == 0) ? finf() : __ldg(s + gelem - 1);
    const float rlast = (gelem + 4 * STR_F4_PER_WARP == BFT)
                            ? finf()
                            : __ldg(s + gelem + 4 * STR_F4_PER_WARP);
    float4 v = p4[lane];
#pragma unroll
    for (int it = 0; it < 5; ++it) {
        float4 vn = v;
        if (it < 4) vn = p4[(it + 1) * 32 + lane];
        float l = __shfl_up_sync(FULLM, v.w, 1);
        if (lane == 0) l = carry;
        float r = __shfl_down_sync(FULLM, v.x, 1);
        float r31 = (it < 4) ? __shfl_sync(FULLM, vn.x, 0) : rlast;
        if (lane == 31) r = r31;
        carry = __shfl_sync(FULLM, v.w, 31);

        unsigned word = nib4(v, l, r) << sh;
        word |= __shfl_xor_sync(FULLM, word, 1);
        word |= __shfl_xor_sync(FULLM, word, 2);
        word |= __shfl_xor_sync(FULLM, word, 4);
        if ((lane & 7) == 0) wp[it * 4] = word;
        v = vn;
    }
}

// ---------------------------------------------------------------------------
// Aux kernel: 10240 blocks (2048 pairs x 5 fifths), 256 threads.
// __launch_bounds__(256, 4): occ cap 4 is LOAD-BEARING — R6 measured occ-8 at
// DRAM 68.7% vs occ-4's ~88% (cross-CTA L1tex-queue contention; oe*MLP_p1).
// Streams 10240 elements/block evict-first, ANDs peak nibbles against the
// L2-resident strain bitset, writes 3 int partials. The LAST block (atomic
// ticket) sums all partials, writes the 4096 outputs, resets the ticket.
// ---------------------------------------------------------------------------
__global__ __launch_bounds__(256, 4) void aux_kernel(const float* __restrict__ aux,
                                                     float* __restrict__ out,
                                                     int half) {
    const int blk = blockIdx.x;
    const int pair = blk / NFIFTH, fifth = blk - pair * NFIFTH;
    const int b = pair & 63, n = pair >> 6;
    const int tid = threadIdx.x, lane = tid & 31, w = tid >> 5;

    const float* ch = aux + (size_t)n * BFT;
    const int slab4 = fifth * F4_PER_FIFTH + w * AUX_F4_PER_WARP;
    const int gelem = b * FT + slab4 * 4;
    const float4* p4 = reinterpret_cast<const float4*>(ch + gelem);
    const unsigned* __restrict__ swp = g_sbits + b * WPB + (slab4 >> 3) + (lane >> 3);
    const int sh = (lane & 7) << 2;

    float carry = (gelem == 0) ? finf() : __ldg(ch + gelem - 1);
    const float rlast = (gelem + 4 * AUX_F4_PER_WARP == BFT)
                            ? finf()
                            : __ldg(ch + gelem + 4 * AUX_F4_PER_WARP);
    int inter = 0, c2 = 0, c1a = 0;
    float4 v = __ldcs(&p4[lane]);
#pragma unroll
    for (int it = 0; it < 10; ++it) {
        float4 vn = v;
        if (it < 9) vn = __ldcs(&p4[(it + 1) * 32 + lane]);
        float l = __shfl_up_sync(FULLM, v.w, 1);
        if (lane == 0) l = carry;
        float r = __shfl_down_sync(FULLM, v.x, 1);
        float r31 = (it < 9) ? __shfl_sync(FULLM, vn.x, 0) : rlast;
        if (lane == 31) r = r31;
        carry = __shfl_sync(FULLM, v.w, 31);

        unsigned nib = nib4(v, l, r);
        unsigned sw = __ldg(swp + it * 4);            // 8 lanes broadcast same word
        inter += __popc((sw >> sh) & nib);
        c2 += __popc(nib);
        c1a += __popc(sw);                            // sums to 8*c1 over the slab
        v = vn;
    }

    // Block reduce 3 ints (8 warps).
    __shared__ int sm0[8], sm1[8], sm2[8];
#pragma unroll
    for (int o = 16; o > 0; o >>= 1) {
        inter += __shfl_down_sync(FULLM, inter, o);
        c2    += __shfl_down_sync(FULLM, c2, o);
        c1a   += __shfl_down_sync(FULLM, c1a, o);
    }
    if (lane == 0) { sm0[w] = inter; sm1[w] = c2; sm2[w] = c1a; }
    __syncthreads();
    __shared__ bool isLast;
    if (tid == 0) {
        int a = 0, bb = 0, c = 0;
#pragma unroll
        for (int k = 0; k < 8; ++k) { a += sm0[k]; bb += sm1[k]; c += sm2[k]; }
        g_pi[blk] = a; g_pc[blk] = bb; g_pa[blk] = c;
        __threadfence();
        unsigned t = atomicAdd(&g_done, 1u);
        isLast = (t == AUX_NBLK - 1);
    }
    __syncthreads();

    if (isLast) {
        if (tid == 0) g_done = 0;                     // reset for next replay
        // Finalize all 2048 pairs: 8 per thread.
        for (int idx = tid; idx < NPAIR; idx += 256) {
            int ti = 0, tc = 0, ta = 0;
#pragma unroll
            for (int k = 0; k < NFIFTH; ++k) {
                ti += g_pi[idx * NFIFTH + k];
                tc += g_pc[idx * NFIFTH + k];
                ta += g_pa[idx * NFIFTH + k];
            }
            const int c1 = ta >> 3;
            const int uni = c1 + tc - ti;
            float jac, ratio;
            if (uni == 0) {
                jac = 1.0f; ratio = 1.0f;             // empty-vs-empty
            } else {
                jac = (float)ti / (float)uni;
                ratio = (c1 == 0) ? 0.0f : (float)ti / (float)c1;  // 0/0 -> 0
            }
            out[idx] = jac;
            out[half + idx] = ratio;
        }
    }
}

extern "C" void kernel_launch(void* const* d_in, const int* in_sizes, int n_in,
                              void* d_out, int out_size) {
    const float* strain = (const float*)d_in[0];
    const float* aux    = (const float*)d_in[1];
    if (n_in >= 2 && in_sizes[0] != BFT) {            // defensive order check
        strain = (const float*)d_in[1];
        aux    = (const float*)d_in[0];
    }
    float* out = (float*)d_out;

    strain_kernel<<<STR_NBLK, 256>>>(strain);
    aux_kernel<<<AUX_NBLK, 256>>>(aux, out, out_size >> 1);
}

// round 8
// speedup vs baseline: 1.1411x; 1.0929x over previous
#include <cuda_runtime.h>

// Problem constants (shapes fixed by the dataset)
#define BATCH 64
#define FT    51200            // 80 * 640 elements per (channel,batch) slab
#define BFT   3276800          // 64*80*640 per-channel flattened length
#define NAUX  32
#define WPB   1600             // FT/32 bitset words per batch
#define NPAIR 2048             // NAUX * BATCH
#define NFIFTH 5               // aux slab split
#define F4_PER_FIFTH 2560      // 12800/5
#define AUX_F4_PER_WARP 320    // 2560/8 warps
#define AUX_NBLK (NPAIR * NFIFTH)   // 10240
// Strain: flat over the whole buffer (word index == global_elem/32, batch-free)
#define STR_NBLK 640
#define STR_F4_PER_WARP 160    // 819200 f4 / (640*8 warps)
#define FULLM 0xffffffffu

// Largest float strictly below 20.0f: (x > TH_LT) <=> (x >= 20.0f)
#define TH_LT __int_as_float(0x419FFFFF)

// Scratch (__device__ globals — no allocations). All partials fully
// overwritten every launch -> deterministic across graph replays.
__device__ unsigned g_sbits[BATCH * WPB];
__device__ int g_pi[AUX_NBLK];   // partial intersections
__device__ int g_pc[AUX_NBLK];   // partial aux peak counts
__device__ int g_pa[AUX_NBLK];   // partial 8*c1 accumulators

__device__ __forceinline__ float finf() { return __int_as_float(0x7f800000); }

__device__ __forceinline__ unsigned nib4(float4 v, float l, float r) {
    unsigned b0 = (v.x > fmaxf(fmaxf(l,   v.y), TH_LT)) ? 1u : 0u;
    unsigned b1 = (v.y > fmaxf(fmaxf(v.x, v.z), TH_LT)) ? 2u : 0u;
    unsigned b2 = (v.z > fmaxf(fmaxf(v.y, v.w), TH_LT)) ? 4u : 0u;
    unsigned b3 = (v.w > fmaxf(fmaxf(v.z, r),   TH_LT)) ? 8u : 0u;
    return (b0 | b1) | (b2 | b3);
}

// ---------------------------------------------------------------------------
// Strain kernel: peak bitset, batch-agnostic flat indexing. 640 blocks x 256
// thr, up to 8 blocks/SM (latency-bound: wants warps). Measured ~1.5us in R7.
// ---------------------------------------------------------------------------
__global__ __launch_bounds__(256, 8) void strain_kernel(const float* __restrict__ s) {
    const int tid = threadIdx.x, lane = tid & 31, w = tid >> 5;
    const int warp_id = blockIdx.x * 8 + w;

    const int q0 = warp_id * STR_F4_PER_WARP;        // first global float4
    const int gelem = q0 * 4;
    const float4* p4 = reinterpret_cast<const float4*>(s) + q0;
    unsigned* wp = g_sbits + (q0 >> 3) + (lane >> 3);
    const int sh = (lane & 7) << 2;

    float carry = (gelem == 0) ? finf() : __ldg(s + gelem - 1);
    const float rlast = (gelem + 4 * STR_F4_PER_WARP == BFT)
                            ? finf()
                            : __ldg(s + gelem + 4 * STR_F4_PER_WARP);
    float4 v = p4[lane];
#pragma unroll
    for (int it = 0; it < 5; ++it) {
        float4 vn = v;
        if (it < 4) vn = p4[(it + 1) * 32 + lane];
        float l = __shfl_up_sync(FULLM, v.w, 1);
        if (lane == 0) l = carry;
        float r = __shfl_down_sync(FULLM, v.x, 1);
        float r31 = (it < 4) ? __shfl_sync(FULLM, vn.x, 0) : rlast;
        if (lane == 31) r = r31;
        carry = __shfl_sync(FULLM, v.w, 31);

        unsigned word = nib4(v, l, r) << sh;
        word |= __shfl_xor_sync(FULLM, word, 1);
        word |= __shfl_xor_sync(FULLM, word, 2);
        word |= __shfl_xor_sync(FULLM, word, 4);
        if ((lane & 7) == 0) wp[it * 4] = word;
        v = vn;
    }
}

// ---------------------------------------------------------------------------
// Aux kernel: 10240 blocks (2048 pairs x 5 fifths), 256 threads, occ cap 4
// (LOAD-BEARING: occ-8 measured DRAM 68.7% vs occ-4 ~73-88% — cross-CTA
// L1tex-queue contention). UNFUSED tail: 3 plain partial stores, no atomics /
// fences (R7 measured the fused ticket+finalize costing ~6us in CTA-slot
// drain + serial tail).
// ---------------------------------------------------------------------------
__global__ __launch_bounds__(256, 4) void aux_kernel(const float* __restrict__ aux) {
    const int blk = blockIdx.x;
    const int pair = blk / NFIFTH, fifth = blk - pair * NFIFTH;
    const int b = pair & 63, n = pair >> 6;
    const int tid = threadIdx.x, lane = tid & 31, w = tid >> 5;

    const float* ch = aux + (size_t)n * BFT;
    const int slab4 = fifth * F4_PER_FIFTH + w * AUX_F4_PER_WARP;
    const int gelem = b * FT + slab4 * 4;
    const float4* p4 = reinterpret_cast<const float4*>(ch + gelem);
    const unsigned* __restrict__ swp = g_sbits + b * WPB + (slab4 >> 3) + (lane >> 3);
    const int sh = (lane & 7) << 2;

    float carry = (gelem == 0) ? finf() : __ldg(ch + gelem - 1);
    const float rlast = (gelem + 4 * AUX_F4_PER_WARP == BFT)
                            ? finf()
                            : __ldg(ch + gelem + 4 * AUX_F4_PER_WARP);
    int inter = 0, c2 = 0, c1a = 0;
    float4 v = __ldcs(&p4[lane]);
#pragma unroll
    for (int it = 0; it < 10; ++it) {
        float4 vn = v;
        if (it < 9) vn = __ldcs(&p4[(it + 1) * 32 + lane]);
        float l = __shfl_up_sync(FULLM, v.w, 1);
        if (lane == 0) l = carry;
        float r = __shfl_down_sync(FULLM, v.x, 1);
        float r31 = (it < 9) ? __shfl_sync(FULLM, vn.x, 0) : rlast;
        if (lane == 31) r = r31;
        carry = __shfl_sync(FULLM, v.w, 31);

        unsigned nib = nib4(v, l, r);
        unsigned sw = __ldg(swp + it * 4);            // 8 lanes broadcast same word
        inter += __popc((sw >> sh) & nib);
        c2 += __popc(nib);
        c1a += __popc(sw);                            // sums to 8*c1 over the slab
        v = vn;
    }

    // Block reduce 3 ints (8 warps).
    __shared__ int sm0[8], sm1[8], sm2[8];
#pragma unroll
    for (int o = 16; o > 0; o >>= 1) {
        inter += __shfl_down_sync(FULLM, inter, o);
        c2    += __shfl_down_sync(FULLM, c2, o);
        c1a   += __shfl_down_sync(FULLM, c1a, o);
    }
    if (lane == 0) { sm0[w] = inter; sm1[w] = c2; sm2[w] = c1a; }
    __syncthreads();
    if (tid == 0) {
        int a = 0, bb = 0, c = 0;
#pragma unroll
        for (int k = 0; k < 8; ++k) { a += sm0[k]; bb += sm1[k]; c += sm2[k]; }
        g_pi[blk] = a; g_pc[blk] = bb; g_pa[blk] = c;
    }
}

// ---------------------------------------------------------------------------
// Finalize: 2048 threads; sum 5 partials each, emit jaccard + ratio.
// ---------------------------------------------------------------------------
__global__ void fin_kernel(float* __restrict__ out, int half) {
    const int idx = blockIdx.x * blockDim.x + threadIdx.x;
    if (idx >= NPAIR) return;
    int ti = 0, tc = 0, ta = 0;
#pragma unroll
    for (int k = 0; k < NFIFTH; ++k) {
        ti += g_pi[idx * NFIFTH + k];
        tc += g_pc[idx * NFIFTH + k];
        ta += g_pa[idx * NFIFTH + k];
    }
    const int c1 = ta >> 3;
    const int uni = c1 + tc - ti;
    float jac, ratio;
    if (uni == 0) {
        jac = 1.0f; ratio = 1.0f;                     // empty-vs-empty
    } else {
        jac = (float)ti / (float)uni;
        ratio = (c1 == 0) ? 0.0f : (float)ti / (float)c1;  // nan_to_num(0/0)->0
    }
    out[idx] = jac;
    out[half + idx] = ratio;
}

extern "C" void kernel_launch(void* const* d_in, const int* in_sizes, int n_in,
                              void* d_out, int out_size) {
    const float* strain = (const float*)d_in[0];
    const float* aux    = (const float*)d_in[1];
    if (n_in >= 2 && in_sizes[0] != BFT) {            // defensive order check
        strain = (const float*)d_in[1];
        aux    = (const float*)d_in[0];
    }
    float* out = (float*)d_out;

    strain_kernel<<<STR_NBLK, 256>>>(strain);
    aux_kernel<<<AUX_NBLK, 256>>>(aux);
    fin_kernel<<<2, 1024>>>(out, out_size >> 1);
}

// round 9
// speedup vs baseline: 1.1444x; 1.0029x over previous
#include <cuda_runtime.h>

// Problem constants (shapes fixed by the dataset)
#define BATCH 64
#define FT    51200            // 80 * 640 elements per (channel,batch) slab
#define BFT   3276800          // 64*80*640 per-channel flattened length
#define NAUX  32
#define WPB   1600             // FT/32 bitset words per batch
#define NPAIR 2048             // NAUX * BATCH
#define NFIFTH 5               // aux slab split
#define F4_PER_FIFTH 2560      // 12800/5
#define AUX_F4_PER_WARP 320    // 2560/8 warps
#define AUX_NBLK (NPAIR * NFIFTH)   // 10240
#define STR_NBLK 1600          // 12800 warps x 256 elems = 3276800
#define FULLM 0xffffffffu

// Largest float strictly below 20.0f: (x > TH_LT) <=> (x >= 20.0f)
#define TH_LT __int_as_float(0x419FFFFF)

// Scratch (__device__ globals — no allocations). All partials fully
// overwritten every launch -> deterministic across graph replays.
__device__ unsigned g_sbits[BATCH * WPB];
__device__ int g_pi[AUX_NBLK];   // partial intersections
__device__ int g_pc[AUX_NBLK];   // partial aux peak counts
__device__ int g_pa[AUX_NBLK];   // partial 8*c1 accumulators

__device__ __forceinline__ float finf() { return __int_as_float(0x7f800000); }

__device__ __forceinline__ unsigned nib4(float4 v, float l, float r) {
    unsigned b0 = (v.x > fmaxf(fmaxf(l,   v.y), TH_LT)) ? 1u : 0u;
    unsigned b1 = (v.y > fmaxf(fmaxf(v.x, v.z), TH_LT)) ? 2u : 0u;
    unsigned b2 = (v.z > fmaxf(fmaxf(v.y, v.w), TH_LT)) ? 4u : 0u;
    unsigned b3 = (v.w > fmaxf(fmaxf(v.z, r),   TH_LT)) ? 8u : 0u;
    return (b0 | b1) | (b2 | b3);
}

// ---------------------------------------------------------------------------
// Strain kernel: loop-free, chain-free. Each thread owns 8 contiguous
// elements (2 float4 loads) -> interior neighbors in-register; exactly 2
// shuffles for cross-thread neighbors, 2 scalar loads per warp for warp
// edges, 2 shfl_xor to assemble each 32-bit word from 4 lanes.
// R8 profiled the looped version at 7.1us (occ 46%, grid-limited + serial
// chain); this removes both limits. 1600 blocks x 256 threads.
// ---------------------------------------------------------------------------
__global__ __launch_bounds__(256, 8) void strain_kernel(const float* __restrict__ s) {
    const int tid = threadIdx.x, lane = tid & 31, w = tid >> 5;
    const int warp_id = blockIdx.x * 8 + w;          // 0..12799
    const int q0 = warp_id * 64;                     // first float4 of warp
    const int gelem = q0 * 4;                        // first element of warp (256/warp)
    const float4* p4 = reinterpret_cast<const float4*>(s) + q0;

    const float4 v0 = p4[2 * lane];
    const float4 v1 = p4[2 * lane + 1];

    float l = __shfl_up_sync(FULLM, v1.w, 1);
    if (lane == 0)  l = (gelem == 0) ? finf() : __ldg(s + gelem - 1);
    float r = __shfl_down_sync(FULLM, v0.x, 1);
    if (lane == 31) r = (gelem + 256 == BFT) ? finf() : __ldg(s + gelem + 256);

    const unsigned byte = nib4(v0, l, v1.x) | (nib4(v1, v0.w, r) << 4);
    unsigned word = byte << ((lane & 3) << 3);
    word |= __shfl_xor_sync(FULLM, word, 1);
    word |= __shfl_xor_sync(FULLM, word, 2);
    if ((lane & 3) == 0) g_sbits[(gelem >> 5) + (lane >> 2)] = word;
}

// ---------------------------------------------------------------------------
// Aux kernel: 10240 blocks (2048 pairs x 5 fifths), 256 threads, occ cap 4
// (LOAD-BEARING: occ-8 measured DRAM 68.7% vs occ-4 ~73-88% — cross-CTA
// L1tex-queue contention). Plain partial stores, no atomics/fences (fused
// ticket+finalize measured ~6us slower in R7).
// ---------------------------------------------------------------------------
__global__ __launch_bounds__(256, 4) void aux_kernel(const float* __restrict__ aux) {
    const int blk = blockIdx.x;
    const int pair = blk / NFIFTH, fifth = blk - pair * NFIFTH;
    const int b = pair & 63, n = pair >> 6;
    const int tid = threadIdx.x, lane = tid & 31, w = tid >> 5;

    const float* ch = aux + (size_t)n * BFT;
    const int slab4 = fifth * F4_PER_FIFTH + w * AUX_F4_PER_WARP;
    const int gelem = b * FT + slab4 * 4;
    const float4* p4 = reinterpret_cast<const float4*>(ch + gelem);
    const unsigned* __restrict__ swp = g_sbits + b * WPB + (slab4 >> 3) + (lane >> 3);
    const int sh = (lane & 7) << 2;

    float carry = (gelem == 0) ? finf() : __ldg(ch + gelem - 1);
    const float rlast = (gelem + 4 * AUX_F4_PER_WARP == BFT)
                            ? finf()
                            : __ldg(ch + gelem + 4 * AUX_F4_PER_WARP);
    int inter = 0, c2 = 0, c1a = 0;
    float4 v = __ldcs(&p4[lane]);
#pragma unroll
    for (int it = 0; it < 10; ++it) {
        float4 vn = v;
        if (it < 9) vn = __ldcs(&p4[(it + 1) * 32 + lane]);
        float l = __shfl_up_sync(FULLM, v.w, 1);
        if (lane == 0) l = carry;
        float r = __shfl_down_sync(FULLM, v.x, 1);
        float r31 = (it < 9) ? __shfl_sync(FULLM, vn.x, 0) : rlast;
        if (lane == 31) r = r31;
        carry = __shfl_sync(FULLM, v.w, 31);

        unsigned nib = nib4(v, l, r);
        unsigned sw = __ldg(swp + it * 4);            // 8 lanes broadcast same word
        inter += __popc((sw >> sh) & nib);
        c2 += __popc(nib);
        c1a += __popc(sw);                            // sums to 8*c1 over the slab
        v = vn;
    }

    // Block reduce 3 ints (8 warps).
    __shared__ int sm0[8], sm1[8], sm2[8];
#pragma unroll
    for (int o = 16; o > 0; o >>= 1) {
        inter += __shfl_down_sync(FULLM, inter, o);
        c2    += __shfl_down_sync(FULLM, c2, o);
        c1a   += __shfl_down_sync(FULLM, c1a, o);
    }
    if (lane == 0) { sm0[w] = inter; sm1[w] = c2; sm2[w] = c1a; }
    __syncthreads();
    if (tid == 0) {
        int a = 0, bb = 0, c = 0;
#pragma unroll
        for (int k = 0; k < 8; ++k) { a += sm0[k]; bb += sm1[k]; c += sm2[k]; }
        g_pi[blk] = a; g_pc[blk] = bb; g_pa[blk] = c;
    }
}

// ---------------------------------------------------------------------------
// Finalize: 2048 threads; sum 5 partials each, emit jaccard + ratio.
// ---------------------------------------------------------------------------
__global__ void fin_kernel(float* __restrict__ out, int half) {
    const int idx = blockIdx.x * blockDim.x + threadIdx.x;
    if (idx >= NPAIR) return;
    int ti = 0, tc = 0, ta = 0;
#pragma unroll
    for (int k = 0; k < NFIFTH; ++k) {
        ti += g_pi[idx * NFIFTH + k];
        tc += g_pc[idx * NFIFTH + k];
        ta += g_pa[idx * NFIFTH + k];
    }
    const int c1 = ta >> 3;
    const int uni = c1 + tc - ti;
    float jac, ratio;
    if (uni == 0) {
        jac = 1.0f; ratio = 1.0f;                     // empty-vs-empty
    } else {
        jac = (float)ti / (float)uni;
        ratio = (c1 == 0) ? 0.0f : (float)ti / (float)c1;  // nan_to_num(0/0)->0
    }
    out[idx] = jac;
    out[half + idx] = ratio;
}

extern "C" void kernel_launch(void* const* d_in, const int* in_sizes, int n_in,
                              void* d_out, int out_size) {
    const float* strain = (const float*)d_in[0];
    const float* aux    = (const float*)d_in[1];
    if (n_in >= 2 && in_sizes[0] != BFT) {            // defensive order check
        strain = (const float*)d_in[1];
        aux    = (const float*)d_in[0];
    }
    float* out = (float*)d_out;

    strain_kernel<<<STR_NBLK, 256>>>(strain);
    aux_kernel<<<AUX_NBLK, 256>>>(aux);
    fin_kernel<<<2, 1024>>>(out, out_size >> 1);
}